// round 12
// baseline (speedup 1.0000x reference)
#include <cuda_runtime.h>
#include <cuda_bf16.h>
#include <cstdint>
#include <cstddef>

#define HH 1024
#define II 256
#define OO 256
#define BB 64
#define TT 512
#define SCAN_CTAS 64

// -------- static device scratch ----------
__device__ float g_xproj[(size_t)TT * HH * BB];   // [t][h][b]
__device__ float g_outs [(size_t)TT * OO * BB];   // [t][o][b]
// persistent B-fragment h buffer: [t][hi/lo][kt(64)][nt(8)][lane(32)][reg(2)] u32
__device__ unsigned g_hfrag[(size_t)TT * 65536];
__device__ unsigned g_hflag[8192];                // per-scan-CTA ready flags, 128B apart
__device__ unsigned g_xflag[TT * 32];             // per-t xproj tile counters, 128B apart

// -------- helpers ----------
__device__ __forceinline__ unsigned long long pack2(float w) {
    unsigned long long r; unsigned u = __float_as_uint(w);
    asm("mov.b64 %0, {%1, %1};" : "=l"(r) : "r"(u));
    return r;
}
__device__ __forceinline__ void fma2(unsigned long long& d, unsigned long long a, unsigned long long b) {
    asm("fma.rn.f32x2 %0, %1, %2, %3;" : "=l"(d) : "l"(a), "l"(b), "l"(d));
}
__device__ __forceinline__ void unpack2(float& lo, float& hi, unsigned long long v) {
    unsigned a, b;
    asm("mov.b64 {%0, %1}, %2;" : "=r"(a), "=r"(b) : "l"(v));
    lo = __uint_as_float(a); hi = __uint_as_float(b);
}
__device__ __forceinline__ unsigned ld_acq(const unsigned* p) {
    unsigned v;
    asm volatile("ld.acquire.gpu.global.u32 %0, [%1];" : "=r"(v) : "l"(p) : "memory");
    return v;
}
__device__ __forceinline__ void st_rel(unsigned* p, unsigned v) {
    asm volatile("st.release.gpu.global.u32 [%0], %1;" :: "l"(p), "r"(v) : "memory");
}
__device__ __forceinline__ unsigned pack_bf16x2(float x, float y) {
    return (unsigned)__bfloat16_as_ushort(__float2bfloat16(x))
         | ((unsigned)__bfloat16_as_ushort(__float2bfloat16(y)) << 16);
}
__device__ __forceinline__ void mma_bf16(float* d, const unsigned* a, unsigned b0, unsigned b1) {
    asm volatile(
        "mma.sync.aligned.m16n8k16.row.col.f32.bf16.bf16.f32 "
        "{%0,%1,%2,%3}, {%4,%5,%6,%7}, {%8,%9}, {%0,%1,%2,%3};"
        : "+f"(d[0]), "+f"(d[1]), "+f"(d[2]), "+f"(d[3])
        : "r"(a[0]), "r"(a[1]), "r"(a[2]), "r"(a[3]), "r"(b0), "r"(b1));
}
__device__ __forceinline__ void ldcg_v2(unsigned& a, unsigned& b, const unsigned* p) {
    asm volatile("ld.global.cg.v2.u32 {%0,%1}, [%2];" : "=r"(a), "=r"(b) : "l"(p));
}

// ==========================================================================
// Kernel 0: zero flag state
// ==========================================================================
__global__ void flag_init_kernel() {
    for (int i = threadIdx.x; i < 8192; i += 256) g_hflag[i] = 0u;
    for (int i = threadIdx.x; i < TT * 32; i += 256) g_xflag[i] = 0u;
}

// ==========================================================================
// xproj worker role: tiles (t, hb) of x_proj[t][h][b] = inputs·W_in^T + b_in
// t-ordered so early steps complete first; publishes per-t counters.
// ==========================================================================
__device__ void xproj_worker(float* smem,
                             const float* __restrict__ inp,
                             const float* __restrict__ w_in,
                             const float* __restrict__ b_in,
                             int nworkers, int wcta)
{
    float (*As)[68] = reinterpret_cast<float(*)[68]>(smem);            // [i][h]
    float (*Bs)[68] = reinterpret_cast<float(*)[68]>(smem + 32 * 68);  // [i][b]
    const int tid = threadIdx.x;
    const int hg = tid >> 5;      // 16 groups x 4 h rows
    const int bg = tid & 31;      // b pair

    for (int tile = wcta; tile < 16 * TT; tile += nworkers) {
        const int t = tile >> 4;
        const int hbase = (tile & 15) << 6;

        unsigned long long acc[2][2];
        acc[0][0] = acc[0][1] = acc[1][0] = acc[1][1] = 0ull;

        for (int ic = 0; ic < II; ic += 32) {
#pragma unroll
            for (int n = tid; n < 2048; n += 512) {
                int h = n >> 5, i = n & 31;
                As[i][h] = w_in[(size_t)(hbase + h) * II + ic + i];
            }
#pragma unroll
            for (int n = tid; n < 2048; n += 512) {
                int b = n >> 5, i = n & 31;
                Bs[i][b] = inp[(size_t)b * (TT * II) + (size_t)t * II + ic + i];
            }
            __syncthreads();
#pragma unroll
            for (int i = 0; i < 32; ++i) {
                ulonglong2 w01 = *reinterpret_cast<const ulonglong2*>(&As[i][hg << 2]);
                float2 xv = *reinterpret_cast<const float2*>(&Bs[i][bg << 1]);
                unsigned long long x0 = pack2(xv.x), x1 = pack2(xv.y);
                fma2(acc[0][0], w01.x, x0); fma2(acc[0][1], w01.x, x1);
                fma2(acc[1][0], w01.y, x0); fma2(acc[1][1], w01.y, x1);
            }
            __syncthreads();
        }
#pragma unroll
        for (int p = 0; p < 2; ++p) {
            int h0 = hbase + (hg << 2) + 2 * p;
            float yA0, yA1, yB0, yB1;
            unpack2(yA0, yA1, acc[p][0]);
            unpack2(yB0, yB1, acc[p][1]);
            float bi0 = b_in[h0], bi1 = b_in[h0 + 1];
            size_t base = (size_t)t * (HH * BB) + (size_t)h0 * BB + (bg << 1);
            *reinterpret_cast<float2*>(g_xproj + base)      = make_float2(yA0 + bi0, yB0 + bi0);
            *reinterpret_cast<float2*>(g_xproj + base + BB) = make_float2(yA1 + bi1, yB1 + bi1);
        }
        __syncthreads();
        if (tid == 0) {
            __threadfence();
            atomicAdd(&g_xflag[(unsigned)t << 5], 1u);
        }
    }
}

// ==========================================================================
// Fused kernel: blockIdx < 64 -> scan role (M=32 x q-half, 16 warps = 2mt x 8ksl)
//               blockIdx >= 64 -> xproj worker role
// ==========================================================================
__global__ void __launch_bounds__(512, 1) fused_scan_kernel(
    const float* __restrict__ inp, const float* __restrict__ w_in,
    const float* __restrict__ b_in,
    const float* __restrict__ w_rec, const float* __restrict__ b_rec)
{
    extern __shared__ float smem[];
    if (blockIdx.x >= SCAN_CTAS) {
        xproj_worker(smem, inp, w_in, b_in, gridDim.x - SCAN_CTAS,
                     blockIdx.x - SCAN_CTAS);
        return;
    }

    float* part = smem;                                               // 16*512 floats
    float (*hmat)[33] = reinterpret_cast<float(*)[33]>(smem + 16 * 512);  // [32][33]

    const int tid = threadIdx.x;
    const int w = tid >> 5, lane = tid & 31;
    const int cta = blockIdx.x;               // cta = g*2 + q
    const int g = cta >> 1;                   // row-group: rows [g*32, g*32+32)
    const int q = cta & 1;                    // batch half
    const int mt = w >> 3, ksl = w & 7;
    const int row0 = g << 5;

    // ---- A fragments (hi + lo): warp covers rows [row0+mt*16, +16), kt = ksl*8..+8
    unsigned Ahi[8][4], Alo[8][4];
    {
        const int gid = lane >> 2, tig = lane & 3;
        const int m0 = row0 + mt * 16 + gid, m1 = m0 + 8;
#pragma unroll
        for (int kt = 0; kt < 8; ++kt) {
            const int kb = (ksl * 8 + kt) * 16 + tig * 2;
            const float* r0 = w_rec + (size_t)m0 * HH + kb;
            const float* r1 = w_rec + (size_t)m1 * HH + kb;
            float e[8] = { r0[0], r0[1], r1[0], r1[1], r0[8], r0[9], r1[8], r1[9] };
#pragma unroll
            for (int p = 0; p < 4; ++p) {
                float x = e[2 * p], y = e[2 * p + 1];
                __nv_bfloat16 bx = __float2bfloat16(x), by = __float2bfloat16(y);
                Ahi[kt][p] = (unsigned)__bfloat16_as_ushort(bx)
                           | ((unsigned)__bfloat16_as_ushort(by) << 16);
                Alo[kt][p] = pack_bf16x2(x - __bfloat162float(bx),
                                         y - __bfloat162float(by));
            }
        }
    }

    // ---- epilogue mapping: tid -> slot (nt, L, reg); two m-halves per thread
    const int e_nt = tid >> 7;
    const int e_L  = (tid >> 2) & 31;
    const int e_reg = tid & 3;
    const int e_gid = e_L >> 2, e_tig = e_L & 3;
    const int m_loc = e_gid + ((e_reg >> 1) << 3);     // 0..15
    const int n_loc = e_nt * 8 + e_tig * 2 + (e_reg & 1);
    const int k0g = row0 + m_loc, k1g = k0g + 16;
    const int bgl = q * 32 + n_loc;
    const float br0 = b_rec[k0g], br1 = b_rec[k1g];

    // ---- fragment-store mapping (2 stores per thread, ktl loop) ----
    const int fs_hl  = tid >> 8;
    const int fs_rem = tid & 255;
    const int fs_nt  = fs_rem >> 6;
    const int fs_L   = (fs_rem >> 1) & 31;
    const int fs_reg = fs_rem & 1;
    const int fs_m   = fs_reg * 8 + (fs_L & 3) * 2;
    const int fs_n   = fs_nt * 8 + (fs_L >> 2);

    for (int j = 0; j < TT; ++j) {
        // ---- polls: lanes 0-3 wait h producers; warp0-lane4 waits xproj[t=j]
        if (j > 0 && lane < 4) {
            const unsigned* fp = &g_hflag[(unsigned)(((ksl * 4 + lane) << 1) | q) << 5];
            while (ld_acq(fp) < (unsigned)j) __nanosleep(40);
        }
        if (w == 0 && lane == 4) {
            while (ld_acq(&g_xflag[(unsigned)j << 5]) < 16u) __nanosleep(40);
        }
        __syncwarp();

        float d[4][4];
#pragma unroll
        for (int nt = 0; nt < 4; ++nt)
#pragma unroll
            for (int p = 0; p < 4; ++p) d[nt][p] = 0.f;

        if (j > 0) {
            const size_t rbase = (size_t)(j - 1) * 65536u;
#pragma unroll
            for (int kt = 0; kt < 8; ++kt) {
                const int ktg = ksl * 8 + kt;
                unsigned bhi[4][2], blo[4][2];
#pragma unroll
                for (int nt = 0; nt < 4; ++nt) {
                    const unsigned off = (((unsigned)ktg * 8 + (q * 4 + nt)) * 32 + lane) * 2;
                    ldcg_v2(bhi[nt][0], bhi[nt][1], &g_hfrag[rbase + off]);
                    ldcg_v2(blo[nt][0], blo[nt][1], &g_hfrag[rbase + 32768u + off]);
                }
#pragma unroll
                for (int nt = 0; nt < 4; ++nt)
                    mma_bf16(d[nt], Ahi[kt], bhi[nt][0], bhi[nt][1]);
#pragma unroll
                for (int nt = 0; nt < 4; ++nt)
                    mma_bf16(d[nt], Ahi[kt], blo[nt][0], blo[nt][1]);
#pragma unroll
                for (int nt = 0; nt < 4; ++nt)
                    mma_bf16(d[nt], Alo[kt], bhi[nt][0], bhi[nt][1]);
            }
        }

        // ---- partials [w][nt*128 + lane*4 + p] ----
#pragma unroll
        for (int nt = 0; nt < 4; ++nt)
            *reinterpret_cast<float4*>(&part[w * 512 + nt * 128 + lane * 4]) =
                make_float4(d[nt][0], d[nt][1], d[nt][2], d[nt][3]);
        __syncthreads();

        // ---- xv reads (safe: warp0 polled xflag, barrier passed) ----
        const float xv0 = g_xproj[(size_t)j * (HH * BB) + (size_t)k0g * BB + bgl];
        const float xv1 = g_xproj[(size_t)j * (HH * BB) + (size_t)k1g * BB + bgl];

        // ---- reduce over 8 k-slices per m-half (conflict-free) ----
        float y0 = 0.f, y1 = 0.f;
#pragma unroll
        for (int k2 = 0; k2 < 8; ++k2) {
            y0 += part[k2 * 512 + tid];
            y1 += part[(8 + k2) * 512 + tid];
        }

        const float h0 = fmaxf(y0 + br0 + xv0, 0.0f);
        const float h1 = fmaxf(y1 + br1 + xv1, 0.0f);
        hmat[m_loc][n_loc] = h0;
        hmat[m_loc + 16][n_loc] = h1;
        __syncthreads();

        // ---- coalesced fragment stores (2 u32 per thread) ----
#pragma unroll
        for (int ktl = 0; ktl < 2; ++ktl) {
            const float a = hmat[ktl * 16 + fs_m][fs_n];
            const float b = hmat[ktl * 16 + fs_m + 1][fs_n];
            unsigned val;
            if (fs_hl == 0) {
                val = pack_bf16x2(a, b);
            } else {
                val = pack_bf16x2(a - __bfloat162float(__float2bfloat16(a)),
                                  b - __bfloat162float(__float2bfloat16(b)));
            }
            const unsigned idx =
                ((((unsigned)(g * 2 + ktl)) * 8u + (unsigned)(q * 4 + fs_nt)) * 32u
                 + (unsigned)fs_L) * 2u + (unsigned)fs_reg + (unsigned)fs_hl * 32768u;
            g_hfrag[(size_t)j * 65536u + idx] = val;
        }

        // ---- publish ----
        __syncthreads();
        if (tid == 0)
            st_rel(&g_hflag[(unsigned)cta << 5], (unsigned)(j + 1));
    }
}

// ==========================================================================
// Kernel 2b: out GEMM via mma.sync bf16 3-pass (unchanged from R11).
// ==========================================================================
__global__ void __launch_bounds__(256, 2) outproj_mma_kernel(
    const float* __restrict__ w_out, const float* __restrict__ b_out,
    const float* __restrict__ scale, const float* __restrict__ shift)
{
    extern __shared__ float part[];           // [2][8][1024] = 64KB

    const int tid = threadIdx.x;
    const int ksl = tid >> 5, lane = tid & 31;
    const int og = blockIdx.x;
    const int tc = blockIdx.y;

    unsigned Ahi[8][4], Alo[8][4];
    {
        const int gid = lane >> 2, tig = lane & 3;
        const int m0 = og * 16 + gid, m1 = m0 + 8;
#pragma unroll
        for (int kt = 0; kt < 8; ++kt) {
            const int kb = ksl * 128 + kt * 16 + tig * 2;
            const float* r0 = w_out + (size_t)m0 * HH + kb;
            const float* r1 = w_out + (size_t)m1 * HH + kb;
            float e[8] = { r0[0], r0[1], r1[0], r1[1], r0[8], r0[9], r1[8], r1[9] };
#pragma unroll
            for (int p = 0; p < 4; ++p) {
                float x = e[2 * p], y = e[2 * p + 1];
                __nv_bfloat16 bx = __float2bfloat16(x), by = __float2bfloat16(y);
                Ahi[kt][p] = (unsigned)__bfloat16_as_ushort(bx)
                           | ((unsigned)__bfloat16_as_ushort(by) << 16);
                Alo[kt][p] = pack_bf16x2(x - __bfloat162float(bx),
                                         y - __bfloat162float(by));
            }
        }
    }

    const int s0 = tid << 2;
    const int e_nt = s0 >> 7, e_L = (s0 >> 2) & 31;
    const int o_lo = og * 16 + (e_L >> 2), o_hi = o_lo + 8;
    const int n0 = e_nt * 8 + (e_L & 3) * 2;
    const float sc0 = scale[o_lo], sc1 = scale[o_hi];
    const float bo0 = b_out[o_lo], bo1 = b_out[o_hi];
    const float sh0 = shift[o_lo], sh1 = shift[o_hi];

    for (int tt = 0; tt < 16; ++tt) {
        const int t = tc * 16 + tt;
        const size_t tbase = (size_t)t * 65536u;

        float d[8][4];
#pragma unroll
        for (int nt = 0; nt < 8; ++nt)
#pragma unroll
            for (int p = 0; p < 4; ++p) d[nt][p] = 0.f;

#pragma unroll
        for (int kt = 0; kt < 8; ++kt) {
            const unsigned ktg = (unsigned)(ksl * 8 + kt);
            unsigned bh[8][2];
#pragma unroll
            for (int nt = 0; nt < 8; ++nt) {
                const unsigned off = (ktg * 8 + nt) * 64 + lane * 2;
                bh[nt][0] = g_hfrag[tbase + off];
                bh[nt][1] = g_hfrag[tbase + off + 1];
            }
#pragma unroll
            for (int nt = 0; nt < 8; ++nt)
                mma_bf16(d[nt], Ahi[kt], bh[nt][0], bh[nt][1]);
#pragma unroll
            for (int nt = 0; nt < 8; ++nt)
                mma_bf16(d[nt], Alo[kt], bh[nt][0], bh[nt][1]);
#pragma unroll
            for (int nt = 0; nt < 8; ++nt) {
                const unsigned off = (ktg * 8 + nt) * 64 + lane * 2;
                bh[nt][0] = g_hfrag[tbase + 32768u + off];
                bh[nt][1] = g_hfrag[tbase + 32768u + off + 1];
            }
#pragma unroll
            for (int nt = 0; nt < 8; ++nt)
                mma_bf16(d[nt], Ahi[kt], bh[nt][0], bh[nt][1]);
        }

        float* pb = part + (tt & 1) * 8192;
#pragma unroll
        for (int nt = 0; nt < 8; ++nt)
            *reinterpret_cast<float4*>(&pb[ksl * 1024 + nt * 128 + lane * 4]) =
                make_float4(d[nt][0], d[nt][1], d[nt][2], d[nt][3]);
        __syncthreads();

        float4 acc = make_float4(0.f, 0.f, 0.f, 0.f);
#pragma unroll
        for (int k2 = 0; k2 < 8; ++k2) {
            float4 v = *reinterpret_cast<const float4*>(&pb[k2 * 1024 + s0]);
            acc.x += v.x; acc.y += v.y; acc.z += v.z; acc.w += v.w;
        }
        size_t obase = (size_t)t * (OO * BB) + (size_t)o_lo * BB + n0;
        *reinterpret_cast<float2*>(g_outs + obase) =
            make_float2(sc0 * (acc.x + bo0) - sh0, sc0 * (acc.y + bo0) - sh0);
        *reinterpret_cast<float2*>(g_outs + obase + 8 * BB) =
            make_float2(sc1 * (acc.z + bo1) - sh1, sc1 * (acc.w + bo1) - sh1);
    }
}

// ==========================================================================
// Kernel 3a: outs transpose  g_outs[t][o][b] -> out[b][t*OO + o]
// ==========================================================================
__global__ void transpose_outs_kernel(float* __restrict__ dst)
{
    __shared__ float tile[32][33];
    const int t = blockIdx.z;
    const int r0 = blockIdx.x << 5, c0 = blockIdx.y << 5;
    const int x = threadIdx.x, y = threadIdx.y;
    const float* s = g_outs + (size_t)t * OO * BB;
#pragma unroll
    for (int jj = 0; jj < 32; jj += 8)
        tile[y + jj][x] = s[(size_t)(r0 + y + jj) * BB + c0 + x];
    __syncthreads();
    const size_t TR = (size_t)TT * OO;
#pragma unroll
    for (int jj = 0; jj < 32; jj += 8)
        dst[(size_t)(c0 + y + jj) * TR + (size_t)t * OO + r0 + x] = tile[x][y + jj];
}

// ==========================================================================
// Kernel 3b: hids from fragments  hi+lo -> out[b][t*HH + h]
// ==========================================================================
__global__ void __launch_bounds__(256) transpose_hids_kernel(float* __restrict__ dst)
{
    __shared__ unsigned shi[4096];
    __shared__ unsigned slo[4096];
    const int t = blockIdx.x;
    const int hblk = blockIdx.y;
    const int tid = threadIdx.x;
    const size_t tbase = (size_t)t * 65536u;
    const unsigned fbase = (unsigned)hblk * 4096u;

#pragma unroll
    for (int i = 0; i < 16; ++i) {
        shi[tid + i * 256] = g_hfrag[tbase + fbase + tid + i * 256];
        slo[tid + i * 256] = g_hfrag[tbase + 32768u + fbase + tid + i * 256];
    }
    __syncthreads();

    const unsigned short* uhi = reinterpret_cast<const unsigned short*>(shi);
    const unsigned short* ulo = reinterpret_cast<const unsigned short*>(slo);
    const int h_local = tid & 127;
    const int kt_l = h_local >> 4, m = h_local & 15;
    const int h = hblk * 128 + h_local;
    const unsigned mpart = (((unsigned)(m >> 1) & 3u) * 2u + (unsigned)(m >> 3)) * 2u
                         + (unsigned)(m & 1);
#pragma unroll
    for (int i = 0; i < 32; ++i) {
        const int b = (tid >> 7) + i * 2;
        const unsigned u16 = (((unsigned)(kt_l * 8 + (b >> 3)) * 32u
                             + (unsigned)((b & 7) * 4)) * 2u) * 2u + mpart;
        const float v = __bfloat162float(__ushort_as_bfloat16(uhi[u16]))
                      + __bfloat162float(__ushort_as_bfloat16(ulo[u16]));
        dst[(size_t)b * (TT * HH) + (size_t)t * HH + h] = v;
    }
}

// ==========================================================================
extern "C" void kernel_launch(void* const* d_in, const int* in_sizes, int n_in,
                              void* d_out, int out_size)
{
    (void)in_sizes; (void)n_in; (void)out_size;
    const float* inputs = (const float*)d_in[0];
    const float* w_rec  = (const float*)d_in[1];
    const float* b_rec  = (const float*)d_in[2];
    const float* w_in   = (const float*)d_in[3];
    const float* b_in   = (const float*)d_in[4];
    const float* w_out  = (const float*)d_in[5];
    const float* b_out  = (const float*)d_in[6];
    const float* scale  = (const float*)d_in[7];
    const float* shift  = (const float*)d_in[8];
    float* out = (float*)d_out;

    flag_init_kernel<<<1, 256>>>();

    int dev = 0, sms = 148;
    cudaGetDevice(&dev);
    cudaDeviceGetAttribute(&sms, cudaDevAttrMultiProcessorCount, dev);
    int ncta = sms;
    if (ncta > 152) ncta = 152;
    if (ncta < SCAN_CTAS + 8) ncta = SCAN_CTAS + 8;

    const int smem_bytes = 16 * 512 * 4 + 32 * 33 * 4;   // 36992 (worker needs 17408)
    cudaFuncSetAttribute(fused_scan_kernel,
                         cudaFuncAttributeMaxDynamicSharedMemorySize, smem_bytes);
    fused_scan_kernel<<<ncta, 512, smem_bytes>>>(inputs, w_in, b_in, w_rec, b_rec);

    cudaFuncSetAttribute(outproj_mma_kernel,
                         cudaFuncAttributeMaxDynamicSharedMemorySize, 65536);
    outproj_mma_kernel<<<dim3(16, 32), 256, 65536>>>(w_out, b_out, scale, shift);

    transpose_outs_kernel<<<dim3(OO / 32, BB / 32, TT), dim3(32, 8)>>>(out);
    transpose_hids_kernel<<<dim3(TT, HH / 128), 256>>>(out + (size_t)BB * TT * OO);
}

// round 15
// speedup vs baseline: 1.1781x; 1.1781x over previous
#include <cuda_runtime.h>
#include <cuda_bf16.h>
#include <cstdint>
#include <cstddef>

#define HH 1024
#define II 256
#define OO 256
#define BB 64
#define TT 512

// -------- static device scratch ----------
__device__ float g_xproj[(size_t)TT * HH * BB];   // [t][h][b]
__device__ float g_outs [(size_t)TT * OO * BB];   // [t][o][b]
// persistent B-fragment h buffer: [t][hi/lo][kt(64)][nt(8)][lane(32)][reg(2)] u32
__device__ unsigned g_hfrag[(size_t)TT * 65536];
__device__ unsigned g_hflag[8192];                // per-CTA ready flags, 128B apart

// -------- helpers ----------
__device__ __forceinline__ unsigned ld_acq(const unsigned* p) {
    unsigned v;
    asm volatile("ld.acquire.gpu.global.u32 %0, [%1];" : "=r"(v) : "l"(p) : "memory");
    return v;
}
__device__ __forceinline__ void st_rel(unsigned* p, unsigned v) {
    asm volatile("st.release.gpu.global.u32 [%0], %1;" :: "l"(p), "r"(v) : "memory");
}
__device__ __forceinline__ unsigned pack_bf16x2(float x, float y) {
    return (unsigned)__bfloat16_as_ushort(__float2bfloat16(x))
         | ((unsigned)__bfloat16_as_ushort(__float2bfloat16(y)) << 16);
}
__device__ __forceinline__ void mma_bf16(float* d, const unsigned* a, unsigned b0, unsigned b1) {
    asm volatile(
        "mma.sync.aligned.m16n8k16.row.col.f32.bf16.bf16.f32 "
        "{%0,%1,%2,%3}, {%4,%5,%6,%7}, {%8,%9}, {%0,%1,%2,%3};"
        : "+f"(d[0]), "+f"(d[1]), "+f"(d[2]), "+f"(d[3])
        : "r"(a[0]), "r"(a[1]), "r"(a[2]), "r"(a[3]), "r"(b0), "r"(b1));
}
__device__ __forceinline__ void ldcg_v2(unsigned& a, unsigned& b, const unsigned* p) {
    asm volatile("ld.global.cg.v2.u32 {%0,%1}, [%2];" : "=r"(a), "=r"(b) : "l"(p));
}

// build the 4 A-fragment regs (hi & lo) from two fp32 row pointers at kb
__device__ __forceinline__ void build_afrag(const float* r0, const float* r1,
                                            unsigned* ahi, unsigned* alo) {
    float e[8] = { r0[0], r0[1], r1[0], r1[1], r0[8], r0[9], r1[8], r1[9] };
#pragma unroll
    for (int p = 0; p < 4; ++p) {
        float x = e[2 * p], y = e[2 * p + 1];
        __nv_bfloat16 bx = __float2bfloat16(x), by = __float2bfloat16(y);
        ahi[p] = (unsigned)__bfloat16_as_ushort(bx)
               | ((unsigned)__bfloat16_as_ushort(by) << 16);
        alo[p] = pack_bf16x2(x - __bfloat162float(bx), y - __bfloat162float(by));
    }
}

// ==========================================================================
// Kernel 0: zero flag state
// ==========================================================================
__global__ void flag_init_kernel() {
    for (int i = threadIdx.x; i < 8192; i += 256) g_hflag[i] = 0u;
}

// ==========================================================================
// Kernel 1: xproj via mma.sync bf16 3-pass.
// grid (16 og of M=64, TT/4 tc); 256 thr = 4 m-tiles x 2 k-slices (K=128 each).
// B (inputs) loaded straight from gmem as float2 (coalesced in frag pattern),
// converted to bf16 hi/lo in registers. 2-deep SMEM k-reduction.
// ==========================================================================
__global__ void __launch_bounds__(256, 2) xproj_mma_kernel(
    const float* __restrict__ inp, const float* __restrict__ w_in,
    const float* __restrict__ b_in)
{
    __shared__ float part[8 * 1024];          // [warp][slot] 32KB

    const int tid = threadIdx.x;
    const int w = tid >> 5, lane = tid & 31;
    const int mt = w >> 1, ksl = w & 1;
    const int og = blockIdx.x;                // h rows [og*64, og*64+64)
    const int tc = blockIdx.y;                // t in [tc*4, tc*4+4)
    const int gid = lane >> 2, tig = lane & 3;

    // ---- A fragments (w_in rows m0,m1), 8 kt of 16 within this ksl half ----
    const int m0 = og * 64 + mt * 16 + gid, m1 = m0 + 8;
    unsigned Ahi[8][4], Alo[8][4];
#pragma unroll
    for (int kt = 0; kt < 8; ++kt) {
        const int kb = ksl * 128 + kt * 16 + tig * 2;
        build_afrag(w_in + (size_t)m0 * II + kb, w_in + (size_t)m1 * II + kb,
                    Ahi[kt], Alo[kt]);
    }

    // ---- epilogue constants: thread owns slot range tid*4 in each mt plane
    const int e_L = tid & 31;
    const int e_nt = tid >> 5;                // nt = 0..7
    const int e_b = e_nt * 8 + (e_L & 3) * 2;
    const int e_hoff = (e_L >> 2);
    float bi_lo[4], bi_hi[4];
#pragma unroll
    for (int mi = 0; mi < 4; ++mi) {
        bi_lo[mi] = b_in[og * 64 + mi * 16 + e_hoff];
        bi_hi[mi] = b_in[og * 64 + mi * 16 + e_hoff + 8];
    }

    for (int tt = 0; tt < 4; ++tt) {
        const int t = tc * 4 + tt;

        float d[8][4];
#pragma unroll
        for (int nt = 0; nt < 8; ++nt)
#pragma unroll
            for (int p = 0; p < 4; ++p) d[nt][p] = 0.f;

#pragma unroll
        for (int kt = 0; kt < 8; ++kt) {
            const int kb = ksl * 128 + kt * 16 + tig * 2;
#pragma unroll
            for (int nt = 0; nt < 8; ++nt) {
                const int b = nt * 8 + gid;
                const float* src = inp + (size_t)b * (TT * II) + (size_t)t * II + kb;
                const float2 x0 = *reinterpret_cast<const float2*>(src);
                const float2 x1 = *reinterpret_cast<const float2*>(src + 8);
                const unsigned bhi0 = pack_bf16x2(x0.x, x0.y);
                const unsigned bhi1 = pack_bf16x2(x1.x, x1.y);
                const unsigned blo0 = pack_bf16x2(
                    x0.x - __bfloat162float(__float2bfloat16(x0.x)),
                    x0.y - __bfloat162float(__float2bfloat16(x0.y)));
                const unsigned blo1 = pack_bf16x2(
                    x1.x - __bfloat162float(__float2bfloat16(x1.x)),
                    x1.y - __bfloat162float(__float2bfloat16(x1.y)));
                mma_bf16(d[nt], Ahi[kt], bhi0, bhi1);
                mma_bf16(d[nt], Ahi[kt], blo0, blo1);
                mma_bf16(d[nt], Alo[kt], bhi0, bhi1);
            }
        }

        // ---- partials: [w][nt*128 + lane*4 + p] ----
#pragma unroll
        for (int nt = 0; nt < 8; ++nt)
            *reinterpret_cast<float4*>(&part[w * 1024 + nt * 128 + lane * 4]) =
                make_float4(d[nt][0], d[nt][1], d[nt][2], d[nt][3]);
        __syncthreads();

        // ---- reduce ksl pairs + bias + store (4 mt planes x float4 each) ----
#pragma unroll
        for (int mi = 0; mi < 4; ++mi) {
            const float4 a = *reinterpret_cast<const float4*>(&part[(2 * mi) * 1024 + tid * 4]);
            const float4 c = *reinterpret_cast<const float4*>(&part[(2 * mi + 1) * 1024 + tid * 4]);
            const int h = og * 64 + mi * 16 + e_hoff;
            const size_t base = (size_t)t * (HH * BB) + (size_t)h * BB + e_b;
            *reinterpret_cast<float2*>(g_xproj + base) =
                make_float2(a.x + c.x + bi_lo[mi], a.y + c.y + bi_lo[mi]);
            *reinterpret_cast<float2*>(g_xproj + base + 8 * BB) =
                make_float2(a.z + c.z + bi_hi[mi], a.w + c.w + bi_hi[mi]);
        }
        __syncthreads();
    }
}

// ==========================================================================
// Kernel 2: mma.sync bf16 3-pass recurrent scan (R11-proven).
// 128 CTAs = 64 row-groups (M=16) x 2 batch-halves (N=32).
// ==========================================================================
__global__ void __launch_bounds__(512, 1) rnn_scan_mma_kernel(
    const float* __restrict__ w_rec, const float* __restrict__ b_rec)
{
    __shared__ float part[16 * 512];          // [w][slot] 32KB
    __shared__ float hmat[16][33];            // h matrix for coalesced frag stores

    const int tid = threadIdx.x;
    const int w = tid >> 5;
    const int lane = tid & 31;
    const int cta = blockIdx.x;               // cta = g*2 + q
    const int g = cta >> 1;                   // row-group: rows [g*16, g*16+16)
    const int q = cta & 1;                    // batch half
    const int row0 = g << 4;

    // ---- build A fragments in registers (hi + lo), once ----
    unsigned Ahi[4][4], Alo[4][4];
    {
        const int gid = lane >> 2, tig = lane & 3;
        const int m0 = row0 + gid, m1 = row0 + gid + 8;
#pragma unroll
        for (int kt = 0; kt < 4; ++kt) {
            const int kb = (w * 4 + kt) * 16 + tig * 2;
            build_afrag(w_rec + (size_t)m0 * HH + kb, w_rec + (size_t)m1 * HH + kb,
                        Ahi[kt], Alo[kt]);
        }
    }

    // ---- epilogue slot mapping: tid -> (nt, L, reg) -> (m_local, n_local) ----
    const int ent_nt = tid >> 7;
    const int ent_L  = (tid >> 2) & 31;
    const int ent_reg = tid & 3;
    const int ent_gid = ent_L >> 2, ent_tig = ent_L & 3;
    const int m_local = ent_gid + ((ent_reg >> 1) << 3);
    const int n_local = ent_nt * 8 + ent_tig * 2 + (ent_reg & 1);
    const int k_glob = row0 + m_local;
    const int b_glob = (q << 5) + n_local;
    const float br = b_rec[k_glob];

    // ---- fragment-store role: tid -> (hl, nt_l, L, reg) ----
    const int fs_hl  = tid >> 8;              // 0 = hi, 1 = lo
    const int fs_rem = tid & 255;
    const int fs_nt  = fs_rem >> 6;           // 0..3 (local to q half)
    const int fs_L   = (fs_rem >> 1) & 31;
    const int fs_reg = fs_rem & 1;
    const int fs_m   = fs_reg * 8 + (fs_L & 3) * 2;      // k pair base within kt
    const int fs_n   = fs_nt * 8 + (fs_L >> 2);          // n local to q half
    const unsigned fs_idx = (((unsigned)g * 8u + (unsigned)(q * 4 + fs_nt)) * 32u
                             + (unsigned)fs_L) * 2u + (unsigned)fs_reg
                          + (unsigned)fs_hl * 32768u;

    for (int j = 0; j < TT; ++j) {
        const float xv = g_xproj[(size_t)j * (HH * BB) + (size_t)k_glob * BB + b_glob];

        float d[4][4];
#pragma unroll
        for (int nt = 0; nt < 4; ++nt)
#pragma unroll
            for (int p = 0; p < 4; ++p) d[nt][p] = 0.f;

        if (j > 0) {
            // wait for the 4 producer CTAs of this warp's k-tiles
            if (lane < 4) {
                const unsigned* fp = &g_hflag[(unsigned)(((w * 4 + lane) << 1) | q) << 5];
                while (ld_acq(fp) < (unsigned)j) __nanosleep(40);
            }
            __syncwarp();

            const size_t rbase = (size_t)(j - 1) * 65536u;
#pragma unroll
            for (int kt = 0; kt < 4; ++kt) {
                const int ktg = w * 4 + kt;
                unsigned bhi[4][2], blo[4][2];
#pragma unroll
                for (int nt = 0; nt < 4; ++nt) {
                    const unsigned off = (((unsigned)ktg * 8 + (q * 4 + nt)) * 32 + lane) * 2;
                    ldcg_v2(bhi[nt][0], bhi[nt][1], &g_hfrag[rbase + off]);
                    ldcg_v2(blo[nt][0], blo[nt][1], &g_hfrag[rbase + 32768u + off]);
                }
#pragma unroll
                for (int nt = 0; nt < 4; ++nt)
                    mma_bf16(d[nt], Ahi[kt], bhi[nt][0], bhi[nt][1]);
#pragma unroll
                for (int nt = 0; nt < 4; ++nt)
                    mma_bf16(d[nt], Ahi[kt], blo[nt][0], blo[nt][1]);
#pragma unroll
                for (int nt = 0; nt < 4; ++nt)
                    mma_bf16(d[nt], Alo[kt], bhi[nt][0], bhi[nt][1]);
            }
        }

        // ---- write partials [w][nt*128 + lane*4 + p] ----
#pragma unroll
        for (int nt = 0; nt < 4; ++nt)
            *reinterpret_cast<float4*>(&part[w * 512 + nt * 128 + lane * 4]) =
                make_float4(d[nt][0], d[nt][1], d[nt][2], d[nt][3]);
        __syncthreads();

        // ---- slot-major reduction over 16 warps (conflict-free) ----
        float y = 0.f;
#pragma unroll
        for (int w2 = 0; w2 < 16; ++w2) y += part[w2 * 512 + tid];

        const float h = fmaxf(y + br + xv, 0.0f);
        hmat[m_local][n_local] = h;
        __syncthreads();

        // ---- coalesced fragment store (one u32 per thread) ----
        {
            const float h0 = hmat[fs_m][fs_n];
            const float h1 = hmat[fs_m + 1][fs_n];
            unsigned val;
            if (fs_hl == 0) {
                val = pack_bf16x2(h0, h1);
            } else {
                const float r0 = h0 - __bfloat162float(__float2bfloat16(h0));
                const float r1 = h1 - __bfloat162float(__float2bfloat16(h1));
                val = pack_bf16x2(r0, r1);
            }
            g_hfrag[(size_t)j * 65536u + fs_idx] = val;
        }

        // ---- publish (release store; barrier + release = happens-before) ----
        __syncthreads();
        if (tid == 0)
            st_rel(&g_hflag[(unsigned)cta << 5], (unsigned)(j + 1));
    }
}

// ==========================================================================
// Kernel 2b: out GEMM via mma.sync bf16 3-pass (R11 config).
// ==========================================================================
__global__ void __launch_bounds__(256, 2) outproj_mma_kernel(
    const float* __restrict__ w_out, const float* __restrict__ b_out,
    const float* __restrict__ scale, const float* __restrict__ shift)
{
    extern __shared__ float part[];           // [2][8][1024] = 64KB

    const int tid = threadIdx.x;
    const int ksl = tid >> 5, lane = tid & 31;
    const int og = blockIdx.x;
    const int tc = blockIdx.y;

    unsigned Ahi[8][4], Alo[8][4];
    {
        const int gid = lane >> 2, tig = lane & 3;
        const int m0 = og * 16 + gid, m1 = m0 + 8;
#pragma unroll
        for (int kt = 0; kt < 8; ++kt) {
            const int kb = ksl * 128 + kt * 16 + tig * 2;
            build_afrag(w_out + (size_t)m0 * HH + kb, w_out + (size_t)m1 * HH + kb,
                        Ahi[kt], Alo[kt]);
        }
    }

    const int s0 = tid << 2;
    const int e_nt = s0 >> 7, e_L = (s0 >> 2) & 31;
    const int o_lo = og * 16 + (e_L >> 2), o_hi = o_lo + 8;
    const int n0 = e_nt * 8 + (e_L & 3) * 2;
    const float sc0 = scale[o_lo], sc1 = scale[o_hi];
    const float bo0 = b_out[o_lo], bo1 = b_out[o_hi];
    const float sh0 = shift[o_lo], sh1 = shift[o_hi];

    for (int tt = 0; tt < 16; ++tt) {
        const int t = tc * 16 + tt;
        const size_t tbase = (size_t)t * 65536u;

        float d[8][4];
#pragma unroll
        for (int nt = 0; nt < 8; ++nt)
#pragma unroll
            for (int p = 0; p < 4; ++p) d[nt][p] = 0.f;

#pragma unroll
        for (int kt = 0; kt < 8; ++kt) {
            const unsigned ktg = (unsigned)(ksl * 8 + kt);
            unsigned bh[8][2];
#pragma unroll
            for (int nt = 0; nt < 8; ++nt) {
                const unsigned off = (ktg * 8 + nt) * 64 + lane * 2;
                bh[nt][0] = g_hfrag[tbase + off];
                bh[nt][1] = g_hfrag[tbase + off + 1];
            }
#pragma unroll
            for (int nt = 0; nt < 8; ++nt)
                mma_bf16(d[nt], Ahi[kt], bh[nt][0], bh[nt][1]);
#pragma unroll
            for (int nt = 0; nt < 8; ++nt)
                mma_bf16(d[nt], Alo[kt], bh[nt][0], bh[nt][1]);
#pragma unroll
            for (int nt = 0; nt < 8; ++nt) {
                const unsigned off = (ktg * 8 + nt) * 64 + lane * 2;
                bh[nt][0] = g_hfrag[tbase + 32768u + off];
                bh[nt][1] = g_hfrag[tbase + 32768u + off + 1];
            }
#pragma unroll
            for (int nt = 0; nt < 8; ++nt)
                mma_bf16(d[nt], Ahi[kt], bh[nt][0], bh[nt][1]);
        }

        float* pb = part + (tt & 1) * 8192;
#pragma unroll
        for (int nt = 0; nt < 8; ++nt)
            *reinterpret_cast<float4*>(&pb[ksl * 1024 + nt * 128 + lane * 4]) =
                make_float4(d[nt][0], d[nt][1], d[nt][2], d[nt][3]);
        __syncthreads();

        float4 acc = make_float4(0.f, 0.f, 0.f, 0.f);
#pragma unroll
        for (int k2 = 0; k2 < 8; ++k2) {
            float4 v = *reinterpret_cast<const float4*>(&pb[k2 * 1024 + s0]);
            acc.x += v.x; acc.y += v.y; acc.z += v.z; acc.w += v.w;
        }
        size_t obase = (size_t)t * (OO * BB) + (size_t)o_lo * BB + n0;
        *reinterpret_cast<float2*>(g_outs + obase) =
            make_float2(sc0 * (acc.x + bo0) - sh0, sc0 * (acc.y + bo0) - sh0);
        *reinterpret_cast<float2*>(g_outs + obase + 8 * BB) =
            make_float2(sc1 * (acc.z + bo1) - sh1, sc1 * (acc.w + bo1) - sh1);
    }
}

// ==========================================================================
// Kernel 3a: outs transpose  g_outs[t][o][b] -> out[b][t*OO + o]
// ==========================================================================
__global__ void transpose_outs_kernel(float* __restrict__ dst)
{
    __shared__ float tile[32][33];
    const int t = blockIdx.z;
    const int r0 = blockIdx.x << 5, c0 = blockIdx.y << 5;
    const int x = threadIdx.x, y = threadIdx.y;
    const float* s = g_outs + (size_t)t * OO * BB;
#pragma unroll
    for (int jj = 0; jj < 32; jj += 8)
        tile[y + jj][x] = s[(size_t)(r0 + y + jj) * BB + c0 + x];
    __syncthreads();
    const size_t TR = (size_t)TT * OO;
#pragma unroll
    for (int jj = 0; jj < 32; jj += 8)
        dst[(size_t)(c0 + y + jj) * TR + (size_t)t * OO + r0 + x] = tile[x][y + jj];
}

// ==========================================================================
// Kernel 3b: hids from fragments  hi+lo -> out[b][t*HH + h]
// ==========================================================================
__global__ void __launch_bounds__(256) transpose_hids_kernel(float* __restrict__ dst)
{
    __shared__ unsigned shi[4096];
    __shared__ unsigned slo[4096];
    const int t = blockIdx.x;
    const int hblk = blockIdx.y;
    const int tid = threadIdx.x;
    const size_t tbase = (size_t)t * 65536u;
    const unsigned fbase = (unsigned)hblk * 4096u;

#pragma unroll
    for (int i = 0; i < 16; ++i) {
        shi[tid + i * 256] = g_hfrag[tbase + fbase + tid + i * 256];
        slo[tid + i * 256] = g_hfrag[tbase + 32768u + fbase + tid + i * 256];
    }
    __syncthreads();

    const unsigned short* uhi = reinterpret_cast<const unsigned short*>(shi);
    const unsigned short* ulo = reinterpret_cast<const unsigned short*>(slo);
    const int h_local = tid & 127;
    const int kt_l = h_local >> 4, m = h_local & 15;
    const int h = hblk * 128 + h_local;
    const unsigned mpart = (((unsigned)(m >> 1) & 3u) * 2u + (unsigned)(m >> 3)) * 2u
                         + (unsigned)(m & 1);
#pragma unroll
    for (int i = 0; i < 32; ++i) {
        const int b = (tid >> 7) + i * 2;
        const unsigned u16 = (((unsigned)(kt_l * 8 + (b >> 3)) * 32u
                             + (unsigned)((b & 7) * 4)) * 2u) * 2u + mpart;
        const float v = __bfloat162float(__ushort_as_bfloat16(uhi[u16]))
                      + __bfloat162float(__ushort_as_bfloat16(ulo[u16]));
        dst[(size_t)b * (TT * HH) + (size_t)t * HH + h] = v;
    }
}

// ==========================================================================
extern "C" void kernel_launch(void* const* d_in, const int* in_sizes, int n_in,
                              void* d_out, int out_size)
{
    (void)in_sizes; (void)n_in; (void)out_size;
    const float* inputs = (const float*)d_in[0];
    const float* w_rec  = (const float*)d_in[1];
    const float* b_rec  = (const float*)d_in[2];
    const float* w_in   = (const float*)d_in[3];
    const float* b_in   = (const float*)d_in[4];
    const float* w_out  = (const float*)d_in[5];
    const float* b_out  = (const float*)d_in[6];
    const float* scale  = (const float*)d_in[7];
    const float* shift  = (const float*)d_in[8];
    float* out = (float*)d_out;

    flag_init_kernel<<<1, 256>>>();

    xproj_mma_kernel<<<dim3(16, TT / 4), 256>>>(inputs, w_in, b_in);

    rnn_scan_mma_kernel<<<128, 512>>>(w_rec, b_rec);

    cudaFuncSetAttribute(outproj_mma_kernel,
                         cudaFuncAttributeMaxDynamicSharedMemorySize, 65536);
    outproj_mma_kernel<<<dim3(16, 32), 256, 65536>>>(w_out, b_out, scale, shift);

    transpose_outs_kernel<<<dim3(OO / 32, BB / 32, TT), dim3(32, 8)>>>(out);
    transpose_hids_kernel<<<dim3(TT, HH / 128), 256>>>(out + (size_t)BB * TT * OO);
}